// round 2
// baseline (speedup 1.0000x reference)
#include <cuda_runtime.h>
#include <cuda_fp16.h>
#include <cstdint>

#define NTOK 8192
#define INDIM 256
#define DIM 128
#define DV 144   // padded V1 cols: 0-127 = V, 128 = ones (row-sum col), 129-143 = zero pad
#define QKSCALE 0.08838834764831845f   // 1/sqrt(128)

// ---------------- device scratch (static; no allocations allowed) ----------------
__device__ __half g_feath[NTOK * INDIM];          // feat in fp16                [8192][256]
__device__ __half g_Wt[3 * DIM * INDIM];          // W^T fp16, x=0/1/2 -> q/k/v  [128][256]
__device__ __half g_Q[NTOK * DIM];                // Q row-major                 [8192][128]
__device__ __half g_K[NTOK * DIM];                // K row-major                 [8192][128]
__device__ __half g_Vt[DV * NTOK];                // V1^T: Vt[d][j]              [144][8192]
__device__ __half g_CVt[DV * NTOK];               // (C@V1)^T: CVt[d][k]         [144][8192]
__device__ __half g_P[(size_t)NTOK * NTOK];       // exp(scale*Q@K^T)            [8192][8192]

// ---------------- mma.sync m16n8k16 f16 (f32 accum) ----------------
__device__ __forceinline__ void mma16816(float* c, const unsigned* a, const unsigned* b) {
    asm volatile(
        "mma.sync.aligned.m16n8k16.row.col.f32.f16.f16.f32 "
        "{%0,%1,%2,%3}, {%4,%5,%6,%7}, {%8,%9}, {%0,%1,%2,%3};\n"
        : "+f"(c[0]), "+f"(c[1]), "+f"(c[2]), "+f"(c[3])
        : "r"(a[0]), "r"(a[1]), "r"(a[2]), "r"(a[3]), "r"(b[0]), "r"(b[1]));
}

__device__ __forceinline__ float elu1(float x) { return x > 0.f ? x : expm1f(x); }

// ---------------- prep kernels ----------------
__global__ void prep_feat(const float* __restrict__ feat) {
    int i = blockIdx.x * blockDim.x + threadIdx.x;
    if (i < NTOK * INDIM) g_feath[i] = __float2half(feat[i]);
}

__global__ void prep_w(const float* __restrict__ Wq, const float* __restrict__ Wk,
                       const float* __restrict__ Wv) {
    int i = blockIdx.x * blockDim.x + threadIdx.x;
    if (i >= 3 * DIM * INDIM) return;
    int x = i / (DIM * INDIM);
    int r = i % (DIM * INDIM);
    int n = r / INDIM, k = r % INDIM;
    const float* W = (x == 0) ? Wq : (x == 1) ? Wk : Wv;
    g_Wt[i] = __float2half(W[k * DIM + n]);   // Wt[x][n][k] = W[k][n]
}

__global__ void prep_vt_tail() {
    int i = blockIdx.x * blockDim.x + threadIdx.x;   // 16*8192 elems: rows 128..143
    if (i >= 16 * NTOK) return;
    int r = i / NTOK, m = i % NTOK;
    g_Vt[(size_t)(128 + r) * NTOK + m] = (r == 0) ? __float2half(1.0f) : __float2half(0.0f);
}

// ---------------- QKV projection: out[m][n] = sum_k feath[m][k] * Wt[z][n][k] ----------------
// BM=128 BN=128 BK=64, 256 thr (8 warps: 4m x 2n, warp tile 32x64)
__global__ void qkv_kernel() {
    __shared__ __half As[128][72];
    __shared__ __half Bs[128][72];
    const int tid = threadIdx.x, lane = tid & 31, warp = tid >> 5;
    const int wm = warp >> 1, wn = warp & 1;
    const int z = blockIdx.z;
    const int bm = blockIdx.x * 128;
    const __half* Bg = g_Wt + (size_t)z * DIM * INDIM;

    float acc[2][8][4];
#pragma unroll
    for (int mf = 0; mf < 2; mf++)
#pragma unroll
        for (int nf = 0; nf < 8; nf++)
#pragma unroll
            for (int i = 0; i < 4; i++) acc[mf][nf][i] = 0.f;

    for (int kt = 0; kt < INDIM; kt += 64) {
#pragma unroll
        for (int i = 0; i < 4; i++) {
            int idx = tid + i * 256, r = idx >> 3, c = idx & 7;
            *(uint4*)&As[r][c * 8] = *(const uint4*)&g_feath[(size_t)(bm + r) * INDIM + kt + c * 8];
        }
#pragma unroll
        for (int i = 0; i < 4; i++) {
            int idx = tid + i * 256, r = idx >> 3, c = idx & 7;
            *(uint4*)&Bs[r][c * 8] = *(const uint4*)&Bg[(size_t)r * INDIM + kt + c * 8];
        }
        __syncthreads();
        const int q = (lane & 3) * 2;
#pragma unroll
        for (int kk = 0; kk < 64; kk += 16) {
            unsigned a[2][4];
#pragma unroll
            for (int mf = 0; mf < 2; mf++) {
                int r = wm * 32 + mf * 16 + (lane >> 2);
                a[mf][0] = *(const unsigned*)&As[r][kk + q];
                a[mf][1] = *(const unsigned*)&As[r + 8][kk + q];
                a[mf][2] = *(const unsigned*)&As[r][kk + 8 + q];
                a[mf][3] = *(const unsigned*)&As[r + 8][kk + 8 + q];
            }
#pragma unroll
            for (int nf = 0; nf < 8; nf++) {
                int n = wn * 64 + nf * 8 + (lane >> 2);
                unsigned b[2];
                b[0] = *(const unsigned*)&Bs[n][kk + q];
                b[1] = *(const unsigned*)&Bs[n][kk + 8 + q];
                mma16816(acc[0][nf], a[0], b);
                mma16816(acc[1][nf], a[1], b);
            }
        }
        __syncthreads();
    }
#pragma unroll
    for (int mf = 0; mf < 2; mf++) {
        int r0 = bm + wm * 32 + mf * 16 + (lane >> 2);
#pragma unroll
        for (int nf = 0; nf < 8; nf++) {
            int c0 = wn * 64 + nf * 8 + (lane & 3) * 2;
            if (z == 2) {
                g_Vt[(size_t)c0 * NTOK + r0]           = __float2half(acc[mf][nf][0]);
                g_Vt[(size_t)(c0 + 1) * NTOK + r0]     = __float2half(acc[mf][nf][1]);
                g_Vt[(size_t)c0 * NTOK + r0 + 8]       = __float2half(acc[mf][nf][2]);
                g_Vt[(size_t)(c0 + 1) * NTOK + r0 + 8] = __float2half(acc[mf][nf][3]);
            } else {
                __half* O = (z == 0) ? g_Q : g_K;
                *(__half2*)&O[(size_t)r0 * DIM + c0] =
                    __floats2half2_rn(acc[mf][nf][0], acc[mf][nf][1]);
                *(__half2*)&O[(size_t)(r0 + 8) * DIM + c0] =
                    __floats2half2_rn(acc[mf][nf][2], acc[mf][nf][3]);
            }
        }
    }
}

// ---------------- logits: P[i][j] = exp(scale * Q[i].K[j]) ----------------
// BM=128 BN=128 K=128 (two BK=64 steps), 256 thr, warp tile 32x64
__global__ void logits_kernel() {
    __shared__ __half As[128][72];
    __shared__ __half Bs[128][72];
    const int tid = threadIdx.x, lane = tid & 31, warp = tid >> 5;
    const int wm = warp >> 1, wn = warp & 1;
    const int bm = blockIdx.x * 128, bn = blockIdx.y * 128;

    float acc[2][8][4];
#pragma unroll
    for (int mf = 0; mf < 2; mf++)
#pragma unroll
        for (int nf = 0; nf < 8; nf++)
#pragma unroll
            for (int i = 0; i < 4; i++) acc[mf][nf][i] = 0.f;

    for (int kt = 0; kt < DIM; kt += 64) {
#pragma unroll
        for (int i = 0; i < 4; i++) {
            int idx = tid + i * 256, r = idx >> 3, c = idx & 7;
            *(uint4*)&As[r][c * 8] = *(const uint4*)&g_Q[(size_t)(bm + r) * DIM + kt + c * 8];
        }
#pragma unroll
        for (int i = 0; i < 4; i++) {
            int idx = tid + i * 256, r = idx >> 3, c = idx & 7;
            *(uint4*)&Bs[r][c * 8] = *(const uint4*)&g_K[(size_t)(bn + r) * DIM + kt + c * 8];
        }
        __syncthreads();
        const int q = (lane & 3) * 2;
#pragma unroll
        for (int kk = 0; kk < 64; kk += 16) {
            unsigned a[2][4];
#pragma unroll
            for (int mf = 0; mf < 2; mf++) {
                int r = wm * 32 + mf * 16 + (lane >> 2);
                a[mf][0] = *(const unsigned*)&As[r][kk + q];
                a[mf][1] = *(const unsigned*)&As[r + 8][kk + q];
                a[mf][2] = *(const unsigned*)&As[r][kk + 8 + q];
                a[mf][3] = *(const unsigned*)&As[r + 8][kk + 8 + q];
            }
#pragma unroll
            for (int nf = 0; nf < 8; nf++) {
                int n = wn * 64 + nf * 8 + (lane >> 2);
                unsigned b[2];
                b[0] = *(const unsigned*)&Bs[n][kk + q];
                b[1] = *(const unsigned*)&Bs[n][kk + 8 + q];
                mma16816(acc[0][nf], a[0], b);
                mma16816(acc[1][nf], a[1], b);
            }
        }
        __syncthreads();
    }
#pragma unroll
    for (int mf = 0; mf < 2; mf++) {
        int r0 = bm + wm * 32 + mf * 16 + (lane >> 2);
#pragma unroll
        for (int nf = 0; nf < 8; nf++) {
            int c0 = bn + wn * 64 + nf * 8 + (lane & 3) * 2;
            float e0 = __expf(acc[mf][nf][0] * QKSCALE);
            float e1 = __expf(acc[mf][nf][1] * QKSCALE);
            float e2 = __expf(acc[mf][nf][2] * QKSCALE);
            float e3 = __expf(acc[mf][nf][3] * QKSCALE);
            *(__half2*)&g_P[(size_t)r0 * NTOK + c0] = __floats2half2_rn(e0, e1);
            *(__half2*)&g_P[(size_t)(r0 + 8) * NTOK + c0] = __floats2half2_rn(e2, e3);
        }
    }
}

// ---------------- CV1^T = (C @ [V|1])^T : CVt[d][k] ----------------
// BM=64 BN=144(full) BK=64, 256 thr (8 warps: 4m x 2n, warp tile 16x72), reg-prefetch dbuf
__global__ void cv_kernel(const float* __restrict__ Cg) {
    __shared__ __half As[64][72];
    __shared__ __half Bs[DV][72];
    const int tid = threadIdx.x, lane = tid & 31, warp = tid >> 5;
    const int wm = warp >> 1, wn = warp & 1;   // wm 0..3, wn 0..1
    const int bm = blockIdx.x * 64;

    float acc[9][4];
#pragma unroll
    for (int nf = 0; nf < 9; nf++)
#pragma unroll
        for (int i = 0; i < 4; i++) acc[nf][i] = 0.f;

    float4 pa[4];
    uint4  pb[5];

    // prefetch kt=0
#pragma unroll
    for (int i = 0; i < 4; i++) {
        int idx = tid + i * 256, r = idx >> 4, c = idx & 15;
        pa[i] = *(const float4*)&Cg[(size_t)(bm + r) * NTOK + c * 4];
    }
#pragma unroll
    for (int i = 0; i < 5; i++) {
        int idx = tid + i * 256;
        if (idx < DV * 8) {
            int r = idx >> 3, c = idx & 7;
            pb[i] = *(const uint4*)&g_Vt[(size_t)r * NTOK + c * 8];
        }
    }
#pragma unroll
    for (int i = 0; i < 4; i++) {
        int idx = tid + i * 256, r = idx >> 4, c = idx & 15;
        *(__half2*)&As[r][c * 4]     = __floats2half2_rn(pa[i].x, pa[i].y);
        *(__half2*)&As[r][c * 4 + 2] = __floats2half2_rn(pa[i].z, pa[i].w);
    }
#pragma unroll
    for (int i = 0; i < 5; i++) {
        int idx = tid + i * 256;
        if (idx < DV * 8) { int r = idx >> 3, c = idx & 7; *(uint4*)&Bs[r][c * 8] = pb[i]; }
    }
    __syncthreads();

    for (int it = 0; it < NTOK / 64; it++) {
        int ktn = (it + 1) * 64;
        bool more = (it + 1) < (NTOK / 64);
        if (more) {
#pragma unroll
            for (int i = 0; i < 4; i++) {
                int idx = tid + i * 256, r = idx >> 4, c = idx & 15;
                pa[i] = *(const float4*)&Cg[(size_t)(bm + r) * NTOK + ktn + c * 4];
            }
#pragma unroll
            for (int i = 0; i < 5; i++) {
                int idx = tid + i * 256;
                if (idx < DV * 8) {
                    int r = idx >> 3, c = idx & 7;
                    pb[i] = *(const uint4*)&g_Vt[(size_t)r * NTOK + ktn + c * 8];
                }
            }
        }
        const int q = (lane & 3) * 2;
        const int r = wm * 16 + (lane >> 2);
#pragma unroll
        for (int kk = 0; kk < 64; kk += 16) {
            unsigned a[4];
            a[0] = *(const unsigned*)&As[r][kk + q];
            a[1] = *(const unsigned*)&As[r + 8][kk + q];
            a[2] = *(const unsigned*)&As[r][kk + 8 + q];
            a[3] = *(const unsigned*)&As[r + 8][kk + 8 + q];
#pragma unroll
            for (int nf = 0; nf < 9; nf++) {
                int n = wn * 72 + nf * 8 + (lane >> 2);
                unsigned b[2];
                b[0] = *(const unsigned*)&Bs[n][kk + q];
                b[1] = *(const unsigned*)&Bs[n][kk + 8 + q];
                mma16816(acc[nf], a, b);
            }
        }
        __syncthreads();
        if (more) {
#pragma unroll
            for (int i = 0; i < 4; i++) {
                int idx = tid + i * 256, r2 = idx >> 4, c = idx & 15;
                *(__half2*)&As[r2][c * 4]     = __floats2half2_rn(pa[i].x, pa[i].y);
                *(__half2*)&As[r2][c * 4 + 2] = __floats2half2_rn(pa[i].z, pa[i].w);
            }
#pragma unroll
            for (int i = 0; i < 5; i++) {
                int idx = tid + i * 256;
                if (idx < DV * 8) { int r2 = idx >> 3, c = idx & 7; *(uint4*)&Bs[r2][c * 8] = pb[i]; }
            }
            __syncthreads();
        }
    }

    int r0 = bm + wm * 16 + (lane >> 2);
#pragma unroll
    for (int nf = 0; nf < 9; nf++) {
        int c0 = wn * 72 + nf * 8 + (lane & 3) * 2;
        g_CVt[(size_t)c0 * NTOK + r0]           = __float2half(acc[nf][0]);
        g_CVt[(size_t)(c0 + 1) * NTOK + r0]     = __float2half(acc[nf][1]);
        g_CVt[(size_t)c0 * NTOK + r0 + 8]       = __float2half(acc[nf][2]);
        g_CVt[(size_t)(c0 + 1) * NTOK + r0 + 8] = __float2half(acc[nf][3]);
    }
}

// ---------------- out = elu( (P @ CV1)[:,0:128] / (P @ CV1)[:,128] ) ----------------
// Same tiling as cv_kernel; A = P (fp16). Denominator = column 128, broadcast via smem.
__global__ void out_kernel(float* __restrict__ out) {
    __shared__ __half As[64][72];
    __shared__ __half Bs[DV][72];
    __shared__ float den_s[64];
    const int tid = threadIdx.x, lane = tid & 31, warp = tid >> 5;
    const int wm = warp >> 1, wn = warp & 1;
    const int bm = blockIdx.x * 64;

    float acc[9][4];
#pragma unroll
    for (int nf = 0; nf < 9; nf++)
#pragma unroll
        for (int i = 0; i < 4; i++) acc[nf][i] = 0.f;

    uint4 pa[2];
    uint4 pb[5];

#pragma unroll
    for (int i = 0; i < 2; i++) {
        int idx = tid + i * 256, r = idx >> 3, c = idx & 7;
        pa[i] = *(const uint4*)&g_P[(size_t)(bm + r) * NTOK + c * 8];
    }
#pragma unroll
    for (int i = 0; i < 5; i++) {
        int idx = tid + i * 256;
        if (idx < DV * 8) {
            int r = idx >> 3, c = idx & 7;
            pb[i] = *(const uint4*)&g_CVt[(size_t)r * NTOK + c * 8];
        }
    }
#pragma unroll
    for (int i = 0; i < 2; i++) {
        int idx = tid + i * 256, r = idx >> 3, c = idx & 7;
        *(uint4*)&As[r][c * 8] = pa[i];
    }
#pragma unroll
    for (int i = 0; i < 5; i++) {
        int idx = tid + i * 256;
        if (idx < DV * 8) { int r = idx >> 3, c = idx & 7; *(uint4*)&Bs[r][c * 8] = pb[i]; }
    }
    __syncthreads();

    for (int it = 0; it < NTOK / 64; it++) {
        int ktn = (it + 1) * 64;
        bool more = (it + 1) < (NTOK / 64);
        if (more) {
#pragma unroll
            for (int i = 0; i < 2; i++) {
                int idx = tid + i * 256, r = idx >> 3, c = idx & 7;
                pa[i] = *(const uint4*)&g_P[(size_t)(bm + r) * NTOK + ktn + c * 8];
            }
#pragma unroll
            for (int i = 0; i < 5; i++) {
                int idx = tid + i * 256;
                if (idx < DV * 8) {
                    int r = idx >> 3, c = idx & 7;
                    pb[i] = *(const uint4*)&g_CVt[(size_t)r * NTOK + ktn + c * 8];
                }
            }
        }
        const int q = (lane & 3) * 2;
        const int r = wm * 16 + (lane >> 2);
#pragma unroll
        for (int kk = 0; kk < 64; kk += 16) {
            unsigned a[4];
            a[0] = *(const unsigned*)&As[r][kk + q];
            a[1] = *(const unsigned*)&As[r + 8][kk + q];
            a[2] = *(const unsigned*)&As[r][kk + 8 + q];
            a[3] = *(const unsigned*)&As[r + 8][kk + 8 + q];
#pragma unroll
            for (int nf = 0; nf < 9; nf++) {
                int n = wn * 72 + nf * 8 + (lane >> 2);
                unsigned b[2];
                b[0] = *(const unsigned*)&Bs[n][kk + q];
                b[1] = *(const unsigned*)&Bs[n][kk + 8 + q];
                mma16816(acc[nf], a, b);
            }
        }
        __syncthreads();
        if (more) {
#pragma unroll
            for (int i = 0; i < 2; i++) {
                int idx = tid + i * 256, r2 = idx >> 3, c = idx & 7;
                *(uint4*)&As[r2][c * 8] = pa[i];
            }
#pragma unroll
            for (int i = 0; i < 5; i++) {
                int idx = tid + i * 256;
                if (idx < DV * 8) { int r2 = idx >> 3, c = idx & 7; *(uint4*)&Bs[r2][c * 8] = pb[i]; }
            }
            __syncthreads();
        }
    }

    // denominator: column 128 lives in wn==1, nf==7, (lane&3)==0 fragment slots
    if (wn == 1 && (lane & 3) == 0) {
        int rl = wm * 16 + (lane >> 2);
        den_s[rl]     = acc[7][0];
        den_s[rl + 8] = acc[7][2];
    }
    __syncthreads();

    int rl = wm * 16 + (lane >> 2);
    float d0 = den_s[rl] + 1e-9f;
    float d1 = den_s[rl + 8] + 1e-9f;
#pragma unroll
    for (int nf = 0; nf < 9; nf++) {
        int c0 = wn * 72 + nf * 8 + (lane & 3) * 2;
        if (c0 < 128) {
            float e0 = elu1(acc[nf][0] / d0);
            float e1 = elu1(acc[nf][1] / d0);
            float e2 = elu1(acc[nf][2] / d1);
            float e3 = elu1(acc[nf][3] / d1);
            *(float2*)&out[(size_t)(bm + rl) * DIM + c0]     = make_float2(e0, e1);
            *(float2*)&out[(size_t)(bm + rl + 8) * DIM + c0] = make_float2(e2, e3);
        }
    }
}

// ---------------- launch ----------------
extern "C" void kernel_launch(void* const* d_in, const int* in_sizes, int n_in,
                              void* d_out, int out_size) {
    const float* feat = (const float*)d_in[0];
    // d_in[1] = bg (unused scalar)
    const float* Cg   = (const float*)d_in[2];
    const float* Wq   = (const float*)d_in[3];
    const float* Wk   = (const float*)d_in[4];
    const float* Wv   = (const float*)d_in[5];
    float* out = (float*)d_out;

    prep_feat<<<(NTOK * INDIM + 255) / 256, 256>>>(feat);
    prep_w<<<(3 * DIM * INDIM + 255) / 256, 256>>>(Wq, Wk, Wv);
    prep_vt_tail<<<(16 * NTOK + 255) / 256, 256>>>();
    qkv_kernel<<<dim3(NTOK / 128, 1, 3), 256>>>();
    logits_kernel<<<dim3(NTOK / 128, NTOK / 128), 256>>>();
    cv_kernel<<<NTOK / 64, 256>>>(Cg);
    out_kernel<<<NTOK / 64, 256>>>(out);
}

// round 3
// speedup vs baseline: 1.0458x; 1.0458x over previous
#include <cuda_runtime.h>
#include <cuda_fp16.h>
#include <cstdint>

#define NTOK 8192
#define INDIM 256
#define DIM 128
#define FDV 136   // V(128) + ones col(128) ... wait: cols 0-127 = V, col 128 = ones, 129-135 zero pad
#define NSPLIT 8
#define QKSCALE 0.08838834764831845f   // 1/sqrt(128), folded into Wq at prep

// ---------------- device scratch ----------------
__device__ __half g_feath[NTOK * INDIM];
__device__ __half g_Wt[3 * DIM * INDIM];
__device__ __half g_Q[NTOK * DIM];                 // already scaled by QKSCALE (via Wq)
__device__ __half g_K[NTOK * DIM];
__device__ __half g_Vt[FDV * NTOK];                // V1^T [136][8192]
__device__ __half g_CVt[FDV * NTOK];               // (C@V1)^T [136][8192]
__device__ float  g_scr[(size_t)NSPLIT * NTOK * FDV];  // split partials (reused by cv then fa)

// ---------------- helpers ----------------
__device__ __forceinline__ void mma16816(float* c, const unsigned* a, const unsigned* b) {
    asm volatile(
        "mma.sync.aligned.m16n8k16.row.col.f32.f16.f16.f32 "
        "{%0,%1,%2,%3}, {%4,%5,%6,%7}, {%8,%9}, {%0,%1,%2,%3};\n"
        : "+f"(c[0]), "+f"(c[1]), "+f"(c[2]), "+f"(c[3])
        : "r"(a[0]), "r"(a[1]), "r"(a[2]), "r"(a[3]), "r"(b[0]), "r"(b[1]));
}
__device__ __forceinline__ unsigned smem_u32(const void* p) {
    return static_cast<unsigned>(__cvta_generic_to_shared(p));
}
__device__ __forceinline__ void ldsm4(unsigned& r0, unsigned& r1, unsigned& r2, unsigned& r3,
                                      const void* p) {
    unsigned a = smem_u32(p);
    asm volatile("ldmatrix.sync.aligned.m8n8.x4.shared.b16 {%0,%1,%2,%3}, [%4];"
                 : "=r"(r0), "=r"(r1), "=r"(r2), "=r"(r3) : "r"(a));
}
__device__ __forceinline__ void ldsm2(unsigned& r0, unsigned& r1, const void* p) {
    unsigned a = smem_u32(p);
    asm volatile("ldmatrix.sync.aligned.m8n8.x2.shared.b16 {%0,%1}, [%2];"
                 : "=r"(r0), "=r"(r1) : "r"(a));
}
__device__ __forceinline__ float elu1(float x) { return x > 0.f ? x : expm1f(x); }
__device__ __forceinline__ unsigned packh2(float a, float b) {
    __half2 h = __floats2half2_rn(a, b);
    return *reinterpret_cast<unsigned*>(&h);
}

// ---------------- prep kernels ----------------
__global__ void prep_feat(const float* __restrict__ feat) {
    int i = blockIdx.x * blockDim.x + threadIdx.x;
    if (i < NTOK * INDIM) g_feath[i] = __float2half(feat[i]);
}

__global__ void prep_w(const float* __restrict__ Wq, const float* __restrict__ Wk,
                       const float* __restrict__ Wv) {
    int i = blockIdx.x * blockDim.x + threadIdx.x;
    if (i >= 3 * DIM * INDIM) return;
    int x = i / (DIM * INDIM);
    int r = i % (DIM * INDIM);
    int n = r / INDIM, k = r % INDIM;
    const float* W = (x == 0) ? Wq : (x == 1) ? Wk : Wv;
    float v = W[k * DIM + n];
    if (x == 0) v *= QKSCALE;          // fold softmax scale into Wq
    g_Wt[i] = __float2half(v);
}

__global__ void prep_vt_tail() {
    int i = blockIdx.x * blockDim.x + threadIdx.x;   // rows 128..135 of Vt
    if (i >= 8 * NTOK) return;
    int r = i / NTOK, m = i % NTOK;
    g_Vt[(size_t)(128 + r) * NTOK + m] = (r == 0) ? __float2half(1.0f) : __float2half(0.0f);
}

// ---------------- QKV projection ----------------
__global__ void qkv_kernel() {
    __shared__ __half As[128][72];
    __shared__ __half Bs[128][72];
    const int tid = threadIdx.x, lane = tid & 31, warp = tid >> 5;
    const int wm = warp >> 1, wn = warp & 1;
    const int z = blockIdx.z;
    const int bm = blockIdx.x * 128;
    const __half* Bg = g_Wt + (size_t)z * DIM * INDIM;

    float acc[2][8][4];
#pragma unroll
    for (int mf = 0; mf < 2; mf++)
#pragma unroll
        for (int nf = 0; nf < 8; nf++)
#pragma unroll
            for (int i = 0; i < 4; i++) acc[mf][nf][i] = 0.f;

    for (int kt = 0; kt < INDIM; kt += 64) {
#pragma unroll
        for (int i = 0; i < 4; i++) {
            int idx = tid + i * 256, r = idx >> 3, c = idx & 7;
            *(uint4*)&As[r][c * 8] = *(const uint4*)&g_feath[(size_t)(bm + r) * INDIM + kt + c * 8];
        }
#pragma unroll
        for (int i = 0; i < 4; i++) {
            int idx = tid + i * 256, r = idx >> 3, c = idx & 7;
            *(uint4*)&Bs[r][c * 8] = *(const uint4*)&Bg[(size_t)r * INDIM + kt + c * 8];
        }
        __syncthreads();
        const int q = (lane & 3) * 2;
#pragma unroll
        for (int kk = 0; kk < 64; kk += 16) {
            unsigned a[2][4];
#pragma unroll
            for (int mf = 0; mf < 2; mf++) {
                int r = wm * 32 + mf * 16 + (lane >> 2);
                a[mf][0] = *(const unsigned*)&As[r][kk + q];
                a[mf][1] = *(const unsigned*)&As[r + 8][kk + q];
                a[mf][2] = *(const unsigned*)&As[r][kk + 8 + q];
                a[mf][3] = *(const unsigned*)&As[r + 8][kk + 8 + q];
            }
#pragma unroll
            for (int nf = 0; nf < 8; nf++) {
                int n = wn * 64 + nf * 8 + (lane >> 2);
                unsigned b[2];
                b[0] = *(const unsigned*)&Bs[n][kk + q];
                b[1] = *(const unsigned*)&Bs[n][kk + 8 + q];
                mma16816(acc[0][nf], a[0], b);
                mma16816(acc[1][nf], a[1], b);
            }
        }
        __syncthreads();
    }
#pragma unroll
    for (int mf = 0; mf < 2; mf++) {
        int r0 = bm + wm * 32 + mf * 16 + (lane >> 2);
#pragma unroll
        for (int nf = 0; nf < 8; nf++) {
            int c0 = wn * 64 + nf * 8 + (lane & 3) * 2;
            if (z == 2) {
                g_Vt[(size_t)c0 * NTOK + r0]           = __float2half(acc[mf][nf][0]);
                g_Vt[(size_t)(c0 + 1) * NTOK + r0]     = __float2half(acc[mf][nf][1]);
                g_Vt[(size_t)c0 * NTOK + r0 + 8]       = __float2half(acc[mf][nf][2]);
                g_Vt[(size_t)(c0 + 1) * NTOK + r0 + 8] = __float2half(acc[mf][nf][3]);
            } else {
                __half* O = (z == 0) ? g_Q : g_K;
                *(__half2*)&O[(size_t)r0 * DIM + c0] =
                    __floats2half2_rn(acc[mf][nf][0], acc[mf][nf][1]);
                *(__half2*)&O[(size_t)(r0 + 8) * DIM + c0] =
                    __floats2half2_rn(acc[mf][nf][2], acc[mf][nf][3]);
            }
        }
    }
}

// ---------------- CV partial: scr[s][d][m] = C[m, js:js+1024] @ V1[js:js+1024, d] ----------------
__global__ void cv_kernel(const float* __restrict__ Cg) {
    __shared__ union SU {
        struct { __half As[64][72]; __half Bs[FDV][72]; } t;
        float Ts[FDV][66];
    } su;
    const int tid = threadIdx.x, lane = tid & 31, warp = tid >> 5;
    const int wm = warp >> 1, wn = warp & 1;
    const int bm = blockIdx.x * 64;
    const int jbase = blockIdx.y * (NTOK / NSPLIT);
    const int ntiles = 9 - wn;   // wn0: n 0..71 (9 tiles), wn1: n 72..135 (8 tiles)

    float acc[9][4];
#pragma unroll
    for (int nf = 0; nf < 9; nf++)
#pragma unroll
        for (int i = 0; i < 4; i++) acc[nf][i] = 0.f;

    float4 pa[4];
    uint4  pb[5];

#pragma unroll
    for (int i = 0; i < 4; i++) {
        int idx = tid + i * 256, r = idx >> 4, c = idx & 15;
        pa[i] = *(const float4*)&Cg[(size_t)(bm + r) * NTOK + jbase + c * 4];
    }
#pragma unroll
    for (int i = 0; i < 5; i++) {
        int idx = tid + i * 256;
        if (idx < FDV * 8) {
            int r = idx >> 3, c = idx & 7;
            pb[i] = *(const uint4*)&g_Vt[(size_t)r * NTOK + jbase + c * 8];
        }
    }
#pragma unroll
    for (int i = 0; i < 4; i++) {
        int idx = tid + i * 256, r = idx >> 4, c = idx & 15;
        *(__half2*)&su.t.As[r][c * 4]     = __floats2half2_rn(pa[i].x, pa[i].y);
        *(__half2*)&su.t.As[r][c * 4 + 2] = __floats2half2_rn(pa[i].z, pa[i].w);
    }
#pragma unroll
    for (int i = 0; i < 5; i++) {
        int idx = tid + i * 256;
        if (idx < FDV * 8) { int r = idx >> 3, c = idx & 7; *(uint4*)&su.t.Bs[r][c * 8] = pb[i]; }
    }
    __syncthreads();

    const int NCH = (NTOK / NSPLIT) / 64;   // 16 chunks
    for (int it = 0; it < NCH; it++) {
        int ktn = jbase + (it + 1) * 64;
        bool more = (it + 1) < NCH;
        if (more) {
#pragma unroll
            for (int i = 0; i < 4; i++) {
                int idx = tid + i * 256, r = idx >> 4, c = idx & 15;
                pa[i] = *(const float4*)&Cg[(size_t)(bm + r) * NTOK + ktn + c * 4];
            }
#pragma unroll
            for (int i = 0; i < 5; i++) {
                int idx = tid + i * 256;
                if (idx < FDV * 8) {
                    int r = idx >> 3, c = idx & 7;
                    pb[i] = *(const uint4*)&g_Vt[(size_t)r * NTOK + ktn + c * 8];
                }
            }
        }
        const int q = (lane & 3) * 2;
        const int r = wm * 16 + (lane >> 2);
#pragma unroll
        for (int kk = 0; kk < 64; kk += 16) {
            unsigned a[4];
            a[0] = *(const unsigned*)&su.t.As[r][kk + q];
            a[1] = *(const unsigned*)&su.t.As[r + 8][kk + q];
            a[2] = *(const unsigned*)&su.t.As[r][kk + 8 + q];
            a[3] = *(const unsigned*)&su.t.As[r + 8][kk + 8 + q];
            for (int nf = 0; nf < ntiles; nf++) {
                int n = wn * 72 + nf * 8 + (lane >> 2);
                unsigned b[2];
                b[0] = *(const unsigned*)&su.t.Bs[n][kk + q];
                b[1] = *(const unsigned*)&su.t.Bs[n][kk + 8 + q];
                mma16816(acc[nf], a, b);
            }
        }
        __syncthreads();
        if (more) {
#pragma unroll
            for (int i = 0; i < 4; i++) {
                int idx = tid + i * 256, r2 = idx >> 4, c = idx & 15;
                *(__half2*)&su.t.As[r2][c * 4]     = __floats2half2_rn(pa[i].x, pa[i].y);
                *(__half2*)&su.t.As[r2][c * 4 + 2] = __floats2half2_rn(pa[i].z, pa[i].w);
            }
#pragma unroll
            for (int i = 0; i < 5; i++) {
                int idx = tid + i * 256;
                if (idx < FDV * 8) { int r2 = idx >> 3, c = idx & 7; *(uint4*)&su.t.Bs[r2][c * 8] = pb[i]; }
            }
        }
        __syncthreads();
    }

    // transpose via smem for coalesced fp32 partial stores
    {
        int r = wm * 16 + (lane >> 2);
        for (int nf = 0; nf < ntiles; nf++) {
            int c0 = wn * 72 + nf * 8 + (lane & 3) * 2;
            su.Ts[c0][r]         = acc[nf][0];
            su.Ts[c0 + 1][r]     = acc[nf][1];
            su.Ts[c0][r + 8]     = acc[nf][2];
            su.Ts[c0 + 1][r + 8] = acc[nf][3];
        }
    }
    __syncthreads();
    for (int idx = tid; idx < FDV * 32; idx += 256) {
        int d = idx >> 5, mm = (idx & 31) * 2;
        *(float2*)&g_scr[((size_t)blockIdx.y * FDV + d) * NTOK + bm + mm] = *(float2*)&su.Ts[d][mm];
    }
}

// ---------------- reduce cv partials -> fp16 CVt ----------------
__global__ void cvreduce_kernel() {
    int i = blockIdx.x * 256 + threadIdx.x;
    if (i >= FDV * NTOK) return;
    float s = 0.f;
#pragma unroll
    for (int ss = 0; ss < NSPLIT; ss++) s += g_scr[(size_t)ss * FDV * NTOK + i];
    g_CVt[i] = __float2half(s);
}

// ---------------- fused attention: scr[s][m][d] = sum_{j in split s} exp(Q_m.K_j) * CV1t[d][j] ----------------
__global__ void __launch_bounds__(128) fa_kernel() {
    __shared__ __half Ks[64][136];
    __shared__ __half CVs[FDV][72];
    const int tid = threadIdx.x, lane = tid & 31, w = tid >> 5;
    const int bm = blockIdx.x * 64;
    const int jbase = blockIdx.y * (NTOK / NSPLIT);
    const int l7 = lane & 7;

    // stage Q (already scaled), extract A fragments, then reuse Ks for K chunks
#pragma unroll
    for (int i = 0; i < 8; i++) {
        int idx = tid + i * 128, r = idx >> 4, c = idx & 15;
        *(uint4*)&Ks[r][c * 8] = *(const uint4*)&g_Q[(size_t)(bm + r) * DIM + c * 8];
    }
    __syncthreads();
    unsigned aq[8][4];
    {
        int rowA = w * 16 + ((lane >> 3) & 1) * 8 + l7;
        int colA = ((lane >> 4) & 1) * 8;
#pragma unroll
        for (int kk = 0; kk < 8; kk++)
            ldsm4(aq[kk][0], aq[kk][1], aq[kk][2], aq[kk][3], &Ks[rowA][kk * 16 + colA]);
    }
    __syncthreads();

    float acc[17][4];
#pragma unroll
    for (int nf = 0; nf < 17; nf++)
#pragma unroll
        for (int i = 0; i < 4; i++) acc[nf][i] = 0.f;

    const int rB = ((lane >> 4) & 1) * 8 + l7;   // B-operand ldmatrix row-in-group
    const int cB = ((lane >> 3) & 1) * 8;        // B-operand ldmatrix col offset

    for (int it = 0; it < (NTOK / NSPLIT) / 64; it++) {
        int jb = jbase + it * 64;
#pragma unroll
        for (int i = 0; i < 8; i++) {
            int idx = tid + i * 128, r = idx >> 4, c = idx & 15;
            *(uint4*)&Ks[r][c * 8] = *(const uint4*)&g_K[(size_t)(jb + r) * DIM + c * 8];
        }
#pragma unroll
        for (int i = 0; i < 9; i++) {
            int idx = tid + i * 128;
            if (idx < FDV * 8) {
                int r = idx >> 3, c = idx & 7;
                *(uint4*)&CVs[r][c * 8] = *(const uint4*)&g_CVt[(size_t)r * NTOK + jb + c * 8];
            }
        }
        __syncthreads();

        // phase 1: S = exp(Q @ K^T) for 16 rows x 64 keys per warp
        float s4[8][4];
#pragma unroll
        for (int j = 0; j < 8; j++)
#pragma unroll
            for (int i = 0; i < 4; i++) s4[j][i] = 0.f;
#pragma unroll
        for (int kk = 0; kk < 8; kk++) {
#pragma unroll
            for (int j2 = 0; j2 < 4; j2++) {
                unsigned b0, b1, b2, b3;
                ldsm4(b0, b1, b2, b3, &Ks[j2 * 16 + rB][kk * 16 + cB]);
                unsigned p0[2] = {b0, b1}, p1[2] = {b2, b3};
                mma16816(s4[2 * j2], aq[kk], p0);
                mma16816(s4[2 * j2 + 1], aq[kk], p1);
            }
        }
        unsigned sh[8][2];
#pragma unroll
        for (int j = 0; j < 8; j++) {
            sh[j][0] = packh2(__expf(s4[j][0]), __expf(s4[j][1]));
            sh[j][1] = packh2(__expf(s4[j][2]), __expf(s4[j][3]));
        }

        // phase 2: acc += S @ CV1 chunk (n = 136 incl. denominator col 128)
#pragma unroll
        for (int t = 0; t < 4; t++) {
            unsigned A[4] = {sh[2 * t][0], sh[2 * t][1], sh[2 * t + 1][0], sh[2 * t + 1][1]};
#pragma unroll
            for (int n2 = 0; n2 < 8; n2++) {
                unsigned b0, b1, b2, b3;
                ldsm4(b0, b1, b2, b3, &CVs[n2 * 16 + rB][t * 16 + cB]);
                unsigned p0[2] = {b0, b1}, p1[2] = {b2, b3};
                mma16816(acc[2 * n2], A, p0);
                mma16816(acc[2 * n2 + 1], A, p1);
            }
            unsigned c0r, c1r;
            ldsm2(c0r, c1r, &CVs[128 + l7][t * 16 + ((lane >> 3) & 1) * 8]);
            unsigned pd[2] = {c0r, c1r};
            mma16816(acc[16], A, pd);
        }
        __syncthreads();
    }

    // store fp32 partials: scr[s][m][d]
    {
        int r0 = bm + w * 16 + (lane >> 2);
        size_t base = ((size_t)blockIdx.y * NTOK + r0) * FDV;
#pragma unroll
        for (int nf = 0; nf < 17; nf++) {
            int c0 = nf * 8 + (lane & 3) * 2;
            *(float2*)&g_scr[base + c0]           = make_float2(acc[nf][0], acc[nf][1]);
            *(float2*)&g_scr[base + 8 * FDV + c0] = make_float2(acc[nf][2], acc[nf][3]);
        }
    }
}

// ---------------- final reduce: out = elu(num / den) ----------------
__global__ void fareduce_kernel(float* __restrict__ out) {
    int m = blockIdx.x;
    int d = threadIdx.x;   // 128
    float num = 0.f, den = 0.f;
#pragma unroll
    for (int s = 0; s < NSPLIT; s++) {
        size_t b = ((size_t)s * NTOK + m) * FDV;
        num += g_scr[b + d];
        den += g_scr[b + 128];
    }
    out[(size_t)m * DIM + d] = elu1(num / (den + 1e-9f));
}

// ---------------- launch ----------------
extern "C" void kernel_launch(void* const* d_in, const int* in_sizes, int n_in,
                              void* d_out, int out_size) {
    const float* feat = (const float*)d_in[0];
    const float* Cg   = (const float*)d_in[2];
    const float* Wq   = (const float*)d_in[3];
    const float* Wk   = (const float*)d_in[4];
    const float* Wv   = (const float*)d_in[5];
    float* out = (float*)d_out;

    prep_feat<<<(NTOK * INDIM + 255) / 256, 256>>>(feat);
    prep_w<<<(3 * DIM * INDIM + 255) / 256, 256>>>(Wq, Wk, Wv);
    prep_vt_tail<<<(8 * NTOK + 255) / 256, 256>>>();
    qkv_kernel<<<dim3(NTOK / 128, 1, 3), 256>>>();
    cv_kernel<<<dim3(NTOK / 64, NSPLIT), 256>>>(Cg);
    cvreduce_kernel<<<(FDV * NTOK + 255) / 256, 256>>>();
    fa_kernel<<<dim3(NTOK / 64, NSPLIT), 128>>>();
    fareduce_kernel<<<NTOK, DIM>>>(out);
}

// round 6
// speedup vs baseline: 1.6730x; 1.5998x over previous
#include <cuda_runtime.h>
#include <cuda_fp16.h>
#include <cstdint>

#define NTOK 8192
#define INDIM 256
#define DIM 128
#define QKSCALE 0.08838834764831845f
#define FA_NSPLIT 4

// ---------------- device scratch ----------------
__device__ __half g_feath[NTOK * INDIM];
__device__ __half g_Wt[3 * DIM * INDIM];
__device__ __half g_Q[NTOK * DIM];                 // scaled by QKSCALE via Wq
__device__ __half g_K[NTOK * DIM];
__device__ __half g_Vt[136 * NTOK];                // V1^T [136][8192]
__device__ __half g_CVt[136 * NTOK];               // (C@V1)^T [136][8192]
__device__ float  g_scr[FA_NSPLIT * NTOK * 144];   // fa split partials [s][m][144]

// ---------------- helpers ----------------
__device__ __forceinline__ unsigned smem_u32(const void* p) {
    return static_cast<unsigned>(__cvta_generic_to_shared(p));
}
__device__ __forceinline__ float elu1(float x) { return x > 0.f ? x : expm1f(x); }
__device__ __forceinline__ unsigned packh2(float a, float b) {
    __half2 h = __floats2half2_rn(a, b);
    return *reinterpret_cast<unsigned*>(&h);
}
__device__ __forceinline__ void mma16816(float* c, const unsigned* a, const unsigned* b) {
    asm volatile(
        "mma.sync.aligned.m16n8k16.row.col.f32.f16.f16.f32 "
        "{%0,%1,%2,%3}, {%4,%5,%6,%7}, {%8,%9}, {%0,%1,%2,%3};\n"
        : "+f"(c[0]), "+f"(c[1]), "+f"(c[2]), "+f"(c[3])
        : "r"(a[0]), "r"(a[1]), "r"(a[2]), "r"(a[3]), "r"(b[0]), "r"(b[1]));
}
__device__ __forceinline__ void ldsm4(unsigned& r0, unsigned& r1, unsigned& r2, unsigned& r3,
                                      const void* p) {
    unsigned a = smem_u32(p);
    asm volatile("ldmatrix.sync.aligned.m8n8.x4.shared.b16 {%0,%1,%2,%3}, [%4];"
                 : "=r"(r0), "=r"(r1), "=r"(r2), "=r"(r3) : "r"(a));
}
__device__ __forceinline__ void ldsm2(unsigned& r0, unsigned& r1, const void* p) {
    unsigned a = smem_u32(p);
    asm volatile("ldmatrix.sync.aligned.m8n8.x2.shared.b16 {%0,%1}, [%2];"
                 : "=r"(r0), "=r"(r1) : "r"(a));
}
__device__ __forceinline__ void cpa16(void* smem_dst, const void* gsrc) {
    unsigned d = smem_u32(smem_dst);
    asm volatile("cp.async.cg.shared.global [%0], [%1], 16;" :: "r"(d), "l"(gsrc) : "memory");
}
#define CPCOMMIT() asm volatile("cp.async.commit_group;" ::: "memory")
#define CPWAIT0()  asm volatile("cp.async.wait_group 0;" ::: "memory")

// ---------------- prep kernels ----------------
__global__ void prep_feat(const float* __restrict__ feat) {
    int i = blockIdx.x * blockDim.x + threadIdx.x;
    if (i < NTOK * INDIM) g_feath[i] = __float2half(feat[i]);
}
__global__ void prep_w(const float* __restrict__ Wq, const float* __restrict__ Wk,
                       const float* __restrict__ Wv) {
    int i = blockIdx.x * blockDim.x + threadIdx.x;
    if (i >= 3 * DIM * INDIM) return;
    int x = i / (DIM * INDIM);
    int r = i % (DIM * INDIM);
    int n = r / INDIM, k = r % INDIM;
    const float* W = (x == 0) ? Wq : (x == 1) ? Wk : Wv;
    float v = W[k * DIM + n];
    if (x == 0) v *= QKSCALE;
    g_Wt[i] = __float2half(v);
}
__global__ void prep_vt_tail() {
    int i = blockIdx.x * blockDim.x + threadIdx.x;
    if (i >= 8 * NTOK) return;
    int r = i / NTOK, m = i % NTOK;
    g_Vt[(size_t)(128 + r) * NTOK + m] = (r == 0) ? __float2half(1.0f) : __float2half(0.0f);
}

// ---------------- QKV projection ----------------
__global__ void qkv_kernel() {
    __shared__ __half As[128][72];
    __shared__ __half Bs[128][72];
    const int tid = threadIdx.x, lane = tid & 31, warp = tid >> 5;
    const int wm = warp >> 1, wn = warp & 1;
    const int z = blockIdx.z;
    const int bm = blockIdx.x * 128;
    const __half* Bg = g_Wt + (size_t)z * DIM * INDIM;

    float acc[2][8][4];
#pragma unroll
    for (int mf = 0; mf < 2; mf++)
#pragma unroll
        for (int nf = 0; nf < 8; nf++)
#pragma unroll
            for (int i = 0; i < 4; i++) acc[mf][nf][i] = 0.f;

    for (int kt = 0; kt < INDIM; kt += 64) {
#pragma unroll
        for (int i = 0; i < 4; i++) {
            int idx = tid + i * 256, r = idx >> 3, c = idx & 7;
            *(uint4*)&As[r][c * 8] = *(const uint4*)&g_feath[(size_t)(bm + r) * INDIM + kt + c * 8];
        }
#pragma unroll
        for (int i = 0; i < 4; i++) {
            int idx = tid + i * 256, r = idx >> 3, c = idx & 7;
            *(uint4*)&Bs[r][c * 8] = *(const uint4*)&Bg[(size_t)r * INDIM + kt + c * 8];
        }
        __syncthreads();
        const int q = (lane & 3) * 2;
#pragma unroll
        for (int kk = 0; kk < 64; kk += 16) {
            unsigned a[2][4];
#pragma unroll
            for (int mf = 0; mf < 2; mf++) {
                int r = wm * 32 + mf * 16 + (lane >> 2);
                a[mf][0] = *(const unsigned*)&As[r][kk + q];
                a[mf][1] = *(const unsigned*)&As[r + 8][kk + q];
                a[mf][2] = *(const unsigned*)&As[r][kk + 8 + q];
                a[mf][3] = *(const unsigned*)&As[r + 8][kk + 8 + q];
            }
#pragma unroll
            for (int nf = 0; nf < 8; nf++) {
                int n = wn * 64 + nf * 8 + (lane >> 2);
                unsigned b[2];
                b[0] = *(const unsigned*)&Bs[n][kk + q];
                b[1] = *(const unsigned*)&Bs[n][kk + 8 + q];
                mma16816(acc[0][nf], a[0], b);
                mma16816(acc[1][nf], a[1], b);
            }
        }
        __syncthreads();
    }
#pragma unroll
    for (int mf = 0; mf < 2; mf++) {
        int r0 = bm + wm * 32 + mf * 16 + (lane >> 2);
#pragma unroll
        for (int nf = 0; nf < 8; nf++) {
            int c0 = wn * 64 + nf * 8 + (lane & 3) * 2;
            if (z == 2) {
                g_Vt[(size_t)c0 * NTOK + r0]           = __float2half(acc[mf][nf][0]);
                g_Vt[(size_t)(c0 + 1) * NTOK + r0]     = __float2half(acc[mf][nf][1]);
                g_Vt[(size_t)c0 * NTOK + r0 + 8]       = __float2half(acc[mf][nf][2]);
                g_Vt[(size_t)(c0 + 1) * NTOK + r0 + 8] = __float2half(acc[mf][nf][3]);
            } else {
                __half* O = (z == 0) ? g_Q : g_K;
                *(__half2*)&O[(size_t)r0 * DIM + c0] =
                    __floats2half2_rn(acc[mf][nf][0], acc[mf][nf][1]);
                *(__half2*)&O[(size_t)(r0 + 8) * DIM + c0] =
                    __floats2half2_rn(acc[mf][nf][2], acc[mf][nf][3]);
            }
        }
    }
}

// n-slice tables for the 2m x 4n warp grid over N=136
__device__ __constant__ int c_noff[4] = {0, 40, 72, 104};

// ---------------- cv: CVt = (C @ V1)^T, fp16 mma, full-K per CTA ----------------
// grid 128: BM=64 rows of C per CTA, 64 iters of 128 keys.
// smem: Cs [64][136]h @0 (17408) | Vs 2x [136][136]h @17408 (36992 each) = 91392
__global__ void __launch_bounds__(256) cv_kernel(const float* __restrict__ Cg) {
    extern __shared__ char sm[];
    char* Cs = sm;
    char* Vs[2] = {sm + 17408, sm + 54400};
    const int tid = threadIdx.x, lane = tid & 31, w = tid >> 5;
    const int mi = w >> 2, ni = w & 3;
    const int bm = blockIdx.x * 64;
    const int noff = c_noff[ni];
    const int nfr = (ni == 0) ? 5 : 4;

    const int rA = ((lane >> 3) & 1) * 8 + (lane & 7);
    const int cA = ((lane >> 4) & 1) * 8;
    const int rB = ((lane >> 4) & 1) * 8 + (lane & 7);
    const int cB = ((lane >> 3) & 1) * 8;
    const int rB2 = lane & 7;
    const int cB2 = ((lane >> 3) & 1) * 8;

    float acc[2][5][4];
#pragma unroll
    for (int mf = 0; mf < 2; mf++)
#pragma unroll
        for (int nf = 0; nf < 5; nf++)
#pragma unroll
            for (int i = 0; i < 4; i++) acc[mf][nf][i] = 0.f;

    // prefetch C(0) into regs
    float4 pa[8];
#pragma unroll
    for (int i = 0; i < 8; i++) {
        int idx = tid + i * 256, r = idx >> 5, c4 = (idx & 31) * 4;
        pa[i] = *(const float4*)&Cg[(size_t)(bm + r) * NTOK + c4];
    }
    // issue Vt(0)
#pragma unroll
    for (int i = 0; i < 9; i++) {
        int idx = tid + i * 256;
        if (idx < 2176) {
            int r = idx >> 4, c = idx & 15;
            cpa16(Vs[0] + r * 272 + c * 16, &g_Vt[(size_t)r * NTOK + c * 8]);
        }
    }
    CPCOMMIT();

    for (int j = 0; j < 64; j++) {
        int b = j & 1;
        CPWAIT0();
        __syncthreads();
        if (j + 1 < 64) {
            int jb = (j + 1) * 128;
#pragma unroll
            for (int i = 0; i < 9; i++) {
                int idx = tid + i * 256;
                if (idx < 2176) {
                    int r = idx >> 4, c = idx & 15;
                    cpa16(Vs[b ^ 1] + r * 272 + c * 16, &g_Vt[(size_t)r * NTOK + jb + c * 8]);
                }
            }
            CPCOMMIT();
        }
        // store C regs -> Cs (fp16)
#pragma unroll
        for (int i = 0; i < 8; i++) {
            int idx = tid + i * 256, r = idx >> 5, c4 = (idx & 31) * 4;
            uint2 v;
            v.x = packh2(pa[i].x, pa[i].y);
            v.y = packh2(pa[i].z, pa[i].w);
            *(uint2*)(Cs + r * 272 + c4 * 2) = v;
        }
        // prefetch C(j+1)
        if (j + 1 < 64) {
            int jb = (j + 1) * 128;
#pragma unroll
            for (int i = 0; i < 8; i++) {
                int idx = tid + i * 256, r = idx >> 5, c4 = (idx & 31) * 4;
                pa[i] = *(const float4*)&Cg[(size_t)(bm + r) * NTOK + jb + c4];
            }
        }
        __syncthreads();
        // compute: acc += Cs[mi rows] @ Vs[b]^T slice
#pragma unroll
        for (int kk = 0; kk < 8; kk++) {
            unsigned A0[4], A1[4];
            ldsm4(A0[0], A0[1], A0[2], A0[3], Cs + (mi * 32 + rA) * 272 + (kk * 16 + cA) * 2);
            ldsm4(A1[0], A1[1], A1[2], A1[3], Cs + (mi * 32 + 16 + rA) * 272 + (kk * 16 + cA) * 2);
#pragma unroll
            for (int p = 0; p < 2; p++) {
                unsigned bb[4];
                ldsm4(bb[0], bb[1], bb[2], bb[3],
                      Vs[b] + (noff + p * 16 + rB) * 272 + (kk * 16 + cB) * 2);
                mma16816(acc[0][p * 2], A0, bb);
                mma16816(acc[0][p * 2 + 1], A0, bb + 2);
                mma16816(acc[1][p * 2], A1, bb);
                mma16816(acc[1][p * 2 + 1], A1, bb + 2);
            }
            if (ni == 0) {
                unsigned b2[2];
                ldsm2(b2[0], b2[1], Vs[b] + (32 + rB2) * 272 + (kk * 16 + cB2) * 2);
                mma16816(acc[0][4], A0, b2);
                mma16816(acc[1][4], A1, b2);
            }
        }
    }
    __syncthreads();
    // transpose to T[136][72]h in Vs[0] area, then coalesced store
    __half* T = (__half*)Vs[0];
#pragma unroll
    for (int mf = 0; mf < 2; mf++) {
        int r = mi * 32 + mf * 16 + (lane >> 2);
        for (int nf = 0; nf < nfr; nf++) {
            int c = noff + nf * 8 + (lane & 3) * 2;
            T[c * 72 + r]           = __float2half(acc[mf][nf][0]);
            T[(c + 1) * 72 + r]     = __float2half(acc[mf][nf][1]);
            T[c * 72 + r + 8]       = __float2half(acc[mf][nf][2]);
            T[(c + 1) * 72 + r + 8] = __float2half(acc[mf][nf][3]);
        }
    }
    __syncthreads();
    for (int idx = tid; idx < 136 * 8; idx += 256) {
        int d = idx >> 3, c8 = (idx & 7) * 8;
        *(uint4*)&g_CVt[(size_t)d * NTOK + bm + c8] = *(uint4*)&T[d * 72 + c8];
    }
}

// ---------------- fused attention ----------------
// grid (128, FA_NSPLIT): BM=64 queries, split keys. 256 thr, warps 2m x 4n, Q in regs.
// smem: Ks 2x34816 @0 | CVs 2x36992 @69632 | S [64][136]h @143616 (17408) = 161024
__global__ void __launch_bounds__(256) fa_kernel() {
    extern __shared__ char sm[];
    char* Ks[2] = {sm, sm + 34816};
    char* CVs[2] = {sm + 69632, sm + 106624};
    char* Ssm = sm + 143616;
    const int tid = threadIdx.x, lane = tid & 31, w = tid >> 5;
    const int mi = w >> 2, ni = w & 3;
    const int bm = blockIdx.x * 64;
    const int jbase = blockIdx.y * (NTOK / FA_NSPLIT);
    const int noff = c_noff[ni];
    const int nfr = (ni == 0) ? 5 : 4;

    const int rA = ((lane >> 3) & 1) * 8 + (lane & 7);
    const int cA = ((lane >> 4) & 1) * 8;
    const int rB = ((lane >> 4) & 1) * 8 + (lane & 7);
    const int cB = ((lane >> 3) & 1) * 8;
    const int rB2 = lane & 7;
    const int cB2 = ((lane >> 3) & 1) * 8;

    // stage Q into S area, extract fragments
#pragma unroll
    for (int i = 0; i < 4; i++) {
        int idx = tid + i * 256, r = idx >> 4, c = idx & 15;
        *(uint4*)(Ssm + r * 272 + c * 16) = *(const uint4*)&g_Q[(size_t)(bm + r) * DIM + c * 8];
    }
    // issue K(0), CV(0)
#pragma unroll
    for (int i = 0; i < 8; i++) {
        int idx = tid + i * 256, r = idx >> 4, c = idx & 15;
        cpa16(Ks[0] + r * 272 + c * 16, &g_K[(size_t)(jbase + r) * DIM + c * 8]);
    }
#pragma unroll
    for (int i = 0; i < 9; i++) {
        int idx = tid + i * 256;
        if (idx < 2176) {
            int r = idx >> 4, c = idx & 15;
            cpa16(CVs[0] + r * 272 + c * 16, &g_CVt[(size_t)r * NTOK + jbase + c * 8]);
        }
    }
    CPCOMMIT();
    __syncthreads();
    unsigned aq[2][8][4];
#pragma unroll
    for (int mf = 0; mf < 2; mf++)
#pragma unroll
        for (int kf = 0; kf < 8; kf++)
            ldsm4(aq[mf][kf][0], aq[mf][kf][1], aq[mf][kf][2], aq[mf][kf][3],
                  Ssm + (mi * 32 + mf * 16 + rA) * 272 + (kf * 16 + cA) * 2);

    float acc[2][5][4];
#pragma unroll
    for (int mf = 0; mf < 2; mf++)
#pragma unroll
        for (int nf = 0; nf < 5; nf++)
#pragma unroll
            for (int i = 0; i < 4; i++) acc[mf][nf][i] = 0.f;

    const int NIT = (NTOK / FA_NSPLIT) / 128;   // 16
    for (int j = 0; j < NIT; j++) {
        int b = j & 1;
        CPWAIT0();
        __syncthreads();
        if (j + 1 < NIT) {
            int jb = jbase + (j + 1) * 128;
#pragma unroll
            for (int i = 0; i < 8; i++) {
                int idx = tid + i * 256, r = idx >> 4, c = idx & 15;
                cpa16(Ks[b ^ 1] + r * 272 + c * 16, &g_K[(size_t)(jb + r) * DIM + c * 8]);
            }
#pragma unroll
            for (int i = 0; i < 9; i++) {
                int idx = tid + i * 256;
                if (idx < 2176) {
                    int r = idx >> 4, c = idx & 15;
                    cpa16(CVs[b ^ 1] + r * 272 + c * 16, &g_CVt[(size_t)r * NTOK + jb + c * 8]);
                }
            }
            CPCOMMIT();
        }
        // phase 1: S = Q @ K^T for this warp's 32 rows x 32 keys
        float sacc[2][4][4];
#pragma unroll
        for (int mf = 0; mf < 2; mf++)
#pragma unroll
            for (int nf = 0; nf < 4; nf++)
#pragma unroll
                for (int i = 0; i < 4; i++) sacc[mf][nf][i] = 0.f;
#pragma unroll
        for (int kk = 0; kk < 8; kk++) {
#pragma unroll
            for (int p = 0; p < 2; p++) {
                unsigned bb[4];
                ldsm4(bb[0], bb[1], bb[2], bb[3],
                      Ks[b] + (ni * 32 + p * 16 + rB) * 272 + (kk * 16 + cB) * 2);
#pragma unroll
                for (int mf = 0; mf < 2; mf++) {
                    mma16816(sacc[mf][p * 2], aq[mf][kk], bb);
                    mma16816(sacc[mf][p * 2 + 1], aq[mf][kk], bb + 2);
                }
            }
        }
        // exp -> fp16 -> S smem
#pragma unroll
        for (int mf = 0; mf < 2; mf++) {
            int r = mi * 32 + mf * 16 + (lane >> 2);
#pragma unroll
            for (int nf = 0; nf < 4; nf++) {
                int c = ni * 32 + nf * 8 + (lane & 3) * 2;
                *(unsigned*)(Ssm + r * 272 + c * 2) =
                    packh2(__expf(sacc[mf][nf][0]), __expf(sacc[mf][nf][1]));
                *(unsigned*)(Ssm + (r + 8) * 272 + c * 2) =
                    packh2(__expf(sacc[mf][nf][2]), __expf(sacc[mf][nf][3]));
            }
        }
        __syncthreads();
        // phase 2: acc += exp(S) @ CV1 slice
#pragma unroll
        for (int kk = 0; kk < 8; kk++) {
            unsigned A0[4], A1[4];
            ldsm4(A0[0], A0[1], A0[2], A0[3], Ssm + (mi * 32 + rA) * 272 + (kk * 16 + cA) * 2);
            ldsm4(A1[0], A1[1], A1[2], A1[3], Ssm + (mi * 32 + 16 + rA) * 272 + (kk * 16 + cA) * 2);
#pragma unroll
            for (int p = 0; p < 2; p++) {
                unsigned bb[4];
                ldsm4(bb[0], bb[1], bb[2], bb[3],
                      CVs[b] + (noff + p * 16 + rB) * 272 + (kk * 16 + cB) * 2);
                mma16816(acc[0][p * 2], A0, bb);
                mma16816(acc[0][p * 2 + 1], A0, bb + 2);
                mma16816(acc[1][p * 2], A1, bb);
                mma16816(acc[1][p * 2 + 1], A1, bb + 2);
            }
            if (ni == 0) {
                unsigned b2[2];
                ldsm2(b2[0], b2[1], CVs[b] + (32 + rB2) * 272 + (kk * 16 + cB2) * 2);
                mma16816(acc[0][4], A0, b2);
                mma16816(acc[1][4], A1, b2);
            }
        }
        __syncthreads();   // S reused next iter
    }
    // store fp32 partials [s][row][144]
#pragma unroll
    for (int mf = 0; mf < 2; mf++) {
        int row = bm + mi * 32 + mf * 16 + (lane >> 2);
        size_t base = ((size_t)blockIdx.y * NTOK + row) * 144;
        for (int nf = 0; nf < nfr; nf++) {
            int c = noff + nf * 8 + (lane & 3) * 2;
            *(float2*)&g_scr[base + c]             = make_float2(acc[mf][nf][0], acc[mf][nf][1]);
            *(float2*)&g_scr[base + 8 * 144 + c]   = make_float2(acc[mf][nf][2], acc[mf][nf][3]);
        }
    }
}

// ---------------- final reduce ----------------
__global__ void fareduce_kernel(float* __restrict__ out) {
    int m = blockIdx.x;
    int d = threadIdx.x;   // 128
    float num = 0.f, den = 0.f;
#pragma unroll
    for (int s = 0; s < FA_NSPLIT; s++) {
        size_t b = ((size_t)s * NTOK + m) * 144;
        num += g_scr[b + d];
        den += g_scr[b + 128];
    }
    out[(size_t)m * DIM + d] = elu1(num / (den + 1e-9f));
}

// ---------------- launch ----------------
extern "C" void kernel_launch(void* const* d_in, const int* in_sizes, int n_in,
                              void* d_out, int out_size) {
    const float* feat = (const float*)d_in[0];
    const float* Cg   = (const float*)d_in[2];
    const float* Wq   = (const float*)d_in[3];
    const float* Wk   = (const float*)d_in[4];
    const float* Wv   = (const float*)d_in[5];
    float* out = (float*)d_out;

    cudaFuncSetAttribute(cv_kernel, cudaFuncAttributeMaxDynamicSharedMemorySize, 91392);
    cudaFuncSetAttribute(fa_kernel, cudaFuncAttributeMaxDynamicSharedMemorySize, 161024);

    prep_feat<<<(NTOK * INDIM + 255) / 256, 256>>>(feat);
    prep_w<<<(3 * DIM * INDIM + 255) / 256, 256>>>(Wq, Wk, Wv);
    prep_vt_tail<<<(8 * NTOK + 255) / 256, 256>>>();
    qkv_kernel<<<dim3(NTOK / 128, 1, 3), 256>>>();
    cv_kernel<<<NTOK / 64, 256, 91392>>>(Cg);
    fa_kernel<<<dim3(NTOK / 64, FA_NSPLIT), 256, 161024>>>();
    fareduce_kernel<<<NTOK, DIM>>>(out);
}

// round 7
// speedup vs baseline: 1.9892x; 1.1890x over previous
#include <cuda_runtime.h>
#include <cuda_fp16.h>
#include <cstdint>

#define NTOK 8192
#define INDIM 256
#define DIM 128
#define QKSCALE 0.08838834764831845f
#define FA_NSPLIT 2

// ---------------- device scratch ----------------
__device__ __half g_feath[NTOK * INDIM];
__device__ __half g_Wt[3 * DIM * INDIM];
__device__ __half g_Q[NTOK * DIM];                 // scaled by QKSCALE via Wq
__device__ __half g_K[NTOK * DIM];
__device__ __half g_Vt[136 * NTOK];                // V1^T [136][8192]
__device__ __half g_CVt[136 * NTOK];               // (C@V1)^T [136][8192]
__device__ float  g_scr[FA_NSPLIT * NTOK * 144];   // fa split partials [s][m][144]

// ---------------- helpers ----------------
__device__ __forceinline__ unsigned smem_u32(const void* p) {
    return static_cast<unsigned>(__cvta_generic_to_shared(p));
}
__device__ __forceinline__ float elu1(float x) { return x > 0.f ? x : expm1f(x); }
__device__ __forceinline__ unsigned packh2(float a, float b) {
    __half2 h = __floats2half2_rn(a, b);
    return *reinterpret_cast<unsigned*>(&h);
}
__device__ __forceinline__ void mma16816(float* c, const unsigned* a, const unsigned* b) {
    asm volatile(
        "mma.sync.aligned.m16n8k16.row.col.f32.f16.f16.f32 "
        "{%0,%1,%2,%3}, {%4,%5,%6,%7}, {%8,%9}, {%0,%1,%2,%3};\n"
        : "+f"(c[0]), "+f"(c[1]), "+f"(c[2]), "+f"(c[3])
        : "r"(a[0]), "r"(a[1]), "r"(a[2]), "r"(a[3]), "r"(b[0]), "r"(b[1]));
}
__device__ __forceinline__ void ldsm4(unsigned& r0, unsigned& r1, unsigned& r2, unsigned& r3,
                                      const void* p) {
    unsigned a = smem_u32(p);
    asm volatile("ldmatrix.sync.aligned.m8n8.x4.shared.b16 {%0,%1,%2,%3}, [%4];"
                 : "=r"(r0), "=r"(r1), "=r"(r2), "=r"(r3) : "r"(a));
}
__device__ __forceinline__ void ldsm2(unsigned& r0, unsigned& r1, const void* p) {
    unsigned a = smem_u32(p);
    asm volatile("ldmatrix.sync.aligned.m8n8.x2.shared.b16 {%0,%1}, [%2];"
                 : "=r"(r0), "=r"(r1) : "r"(a));
}
__device__ __forceinline__ void cpa16(void* smem_dst, const void* gsrc) {
    unsigned d = smem_u32(smem_dst);
    asm volatile("cp.async.cg.shared.global [%0], [%1], 16;" :: "r"(d), "l"(gsrc) : "memory");
}
#define CPCOMMIT() asm volatile("cp.async.commit_group;" ::: "memory")
#define CPWAIT0()  asm volatile("cp.async.wait_group 0;" ::: "memory")

// ---------------- prep kernels ----------------
__global__ void prep_feat(const float* __restrict__ feat) {
    int i = blockIdx.x * blockDim.x + threadIdx.x;
    if (i < NTOK * INDIM) g_feath[i] = __float2half(feat[i]);
}
__global__ void prep_w(const float* __restrict__ Wq, const float* __restrict__ Wk,
                       const float* __restrict__ Wv) {
    int i = blockIdx.x * blockDim.x + threadIdx.x;
    if (i >= 3 * DIM * INDIM) return;
    int x = i / (DIM * INDIM);
    int r = i % (DIM * INDIM);
    int n = r / INDIM, k = r % INDIM;
    const float* W = (x == 0) ? Wq : (x == 1) ? Wk : Wv;
    float v = W[k * DIM + n];
    if (x == 0) v *= QKSCALE;
    g_Wt[i] = __float2half(v);
}
__global__ void prep_vt_tail() {
    int i = blockIdx.x * blockDim.x + threadIdx.x;
    if (i >= 8 * NTOK) return;
    int r = i / NTOK, m = i % NTOK;
    g_Vt[(size_t)(128 + r) * NTOK + m] = (r == 0) ? __float2half(1.0f) : __float2half(0.0f);
}

// ---------------- QKV projection ----------------
__global__ void qkv_kernel() {
    __shared__ __half As[128][72];
    __shared__ __half Bs[128][72];
    const int tid = threadIdx.x, lane = tid & 31, warp = tid >> 5;
    const int wm = warp >> 1, wn = warp & 1;
    const int z = blockIdx.z;
    const int bm = blockIdx.x * 128;
    const __half* Bg = g_Wt + (size_t)z * DIM * INDIM;

    float acc[2][8][4];
#pragma unroll
    for (int mf = 0; mf < 2; mf++)
#pragma unroll
        for (int nf = 0; nf < 8; nf++)
#pragma unroll
            for (int i = 0; i < 4; i++) acc[mf][nf][i] = 0.f;

    for (int kt = 0; kt < INDIM; kt += 64) {
#pragma unroll
        for (int i = 0; i < 4; i++) {
            int idx = tid + i * 256, r = idx >> 3, c = idx & 7;
            *(uint4*)&As[r][c * 8] = *(const uint4*)&g_feath[(size_t)(bm + r) * INDIM + kt + c * 8];
        }
#pragma unroll
        for (int i = 0; i < 4; i++) {
            int idx = tid + i * 256, r = idx >> 3, c = idx & 7;
            *(uint4*)&Bs[r][c * 8] = *(const uint4*)&Bg[(size_t)r * INDIM + kt + c * 8];
        }
        __syncthreads();
        const int q = (lane & 3) * 2;
#pragma unroll
        for (int kk = 0; kk < 64; kk += 16) {
            unsigned a[2][4];
#pragma unroll
            for (int mf = 0; mf < 2; mf++) {
                int r = wm * 32 + mf * 16 + (lane >> 2);
                a[mf][0] = *(const unsigned*)&As[r][kk + q];
                a[mf][1] = *(const unsigned*)&As[r + 8][kk + q];
                a[mf][2] = *(const unsigned*)&As[r][kk + 8 + q];
                a[mf][3] = *(const unsigned*)&As[r + 8][kk + 8 + q];
            }
#pragma unroll
            for (int nf = 0; nf < 8; nf++) {
                int n = wn * 64 + nf * 8 + (lane >> 2);
                unsigned b[2];
                b[0] = *(const unsigned*)&Bs[n][kk + q];
                b[1] = *(const unsigned*)&Bs[n][kk + 8 + q];
                mma16816(acc[0][nf], a[0], b);
                mma16816(acc[1][nf], a[1], b);
            }
        }
        __syncthreads();
    }
#pragma unroll
    for (int mf = 0; mf < 2; mf++) {
        int r0 = bm + wm * 32 + mf * 16 + (lane >> 2);
#pragma unroll
        for (int nf = 0; nf < 8; nf++) {
            int c0 = wn * 64 + nf * 8 + (lane & 3) * 2;
            if (z == 2) {
                g_Vt[(size_t)c0 * NTOK + r0]           = __float2half(acc[mf][nf][0]);
                g_Vt[(size_t)(c0 + 1) * NTOK + r0]     = __float2half(acc[mf][nf][1]);
                g_Vt[(size_t)c0 * NTOK + r0 + 8]       = __float2half(acc[mf][nf][2]);
                g_Vt[(size_t)(c0 + 1) * NTOK + r0 + 8] = __float2half(acc[mf][nf][3]);
            } else {
                __half* O = (z == 0) ? g_Q : g_K;
                *(__half2*)&O[(size_t)r0 * DIM + c0] =
                    __floats2half2_rn(acc[mf][nf][0], acc[mf][nf][1]);
                *(__half2*)&O[(size_t)(r0 + 8) * DIM + c0] =
                    __floats2half2_rn(acc[mf][nf][2], acc[mf][nf][3]);
            }
        }
    }
}

// n-slice tables for cv's 2m x 4n warp grid over N=136
__device__ __constant__ int c_noff[4] = {0, 40, 72, 104};

// ---------------- cv: CVt = (C @ V1)^T (unchanged from R5) ----------------
__global__ void __launch_bounds__(256) cv_kernel(const float* __restrict__ Cg) {
    extern __shared__ char sm[];
    char* Cs = sm;
    char* Vs[2] = {sm + 17408, sm + 54400};
    const int tid = threadIdx.x, lane = tid & 31, w = tid >> 5;
    const int mi = w >> 2, ni = w & 3;
    const int bm = blockIdx.x * 64;
    const int noff = c_noff[ni];
    const int nfr = (ni == 0) ? 5 : 4;

    const int rA = ((lane >> 3) & 1) * 8 + (lane & 7);
    const int cA = ((lane >> 4) & 1) * 8;
    const int rB = ((lane >> 4) & 1) * 8 + (lane & 7);
    const int cB = ((lane >> 3) & 1) * 8;
    const int rB2 = lane & 7;
    const int cB2 = ((lane >> 3) & 1) * 8;

    float acc[2][5][4];
#pragma unroll
    for (int mf = 0; mf < 2; mf++)
#pragma unroll
        for (int nf = 0; nf < 5; nf++)
#pragma unroll
            for (int i = 0; i < 4; i++) acc[mf][nf][i] = 0.f;

    float4 pa[8];
#pragma unroll
    for (int i = 0; i < 8; i++) {
        int idx = tid + i * 256, r = idx >> 5, c4 = (idx & 31) * 4;
        pa[i] = *(const float4*)&Cg[(size_t)(bm + r) * NTOK + c4];
    }
#pragma unroll
    for (int i = 0; i < 9; i++) {
        int idx = tid + i * 256;
        if (idx < 2176) {
            int r = idx >> 4, c = idx & 15;
            cpa16(Vs[0] + r * 272 + c * 16, &g_Vt[(size_t)r * NTOK + c * 8]);
        }
    }
    CPCOMMIT();

    for (int j = 0; j < 64; j++) {
        int b = j & 1;
        CPWAIT0();
        __syncthreads();
        if (j + 1 < 64) {
            int jb = (j + 1) * 128;
#pragma unroll
            for (int i = 0; i < 9; i++) {
                int idx = tid + i * 256;
                if (idx < 2176) {
                    int r = idx >> 4, c = idx & 15;
                    cpa16(Vs[b ^ 1] + r * 272 + c * 16, &g_Vt[(size_t)r * NTOK + jb + c * 8]);
                }
            }
            CPCOMMIT();
        }
#pragma unroll
        for (int i = 0; i < 8; i++) {
            int idx = tid + i * 256, r = idx >> 5, c4 = (idx & 31) * 4;
            uint2 v;
            v.x = packh2(pa[i].x, pa[i].y);
            v.y = packh2(pa[i].z, pa[i].w);
            *(uint2*)(Cs + r * 272 + c4 * 2) = v;
        }
        if (j + 1 < 64) {
            int jb = (j + 1) * 128;
#pragma unroll
            for (int i = 0; i < 8; i++) {
                int idx = tid + i * 256, r = idx >> 5, c4 = (idx & 31) * 4;
                pa[i] = *(const float4*)&Cg[(size_t)(bm + r) * NTOK + jb + c4];
            }
        }
        __syncthreads();
#pragma unroll
        for (int kk = 0; kk < 8; kk++) {
            unsigned A0[4], A1[4];
            ldsm4(A0[0], A0[1], A0[2], A0[3], Cs + (mi * 32 + rA) * 272 + (kk * 16 + cA) * 2);
            ldsm4(A1[0], A1[1], A1[2], A1[3], Cs + (mi * 32 + 16 + rA) * 272 + (kk * 16 + cA) * 2);
#pragma unroll
            for (int p = 0; p < 2; p++) {
                unsigned bb[4];
                ldsm4(bb[0], bb[1], bb[2], bb[3],
                      Vs[b] + (noff + p * 16 + rB) * 272 + (kk * 16 + cB) * 2);
                mma16816(acc[0][p * 2], A0, bb);
                mma16816(acc[0][p * 2 + 1], A0, bb + 2);
                mma16816(acc[1][p * 2], A1, bb);
                mma16816(acc[1][p * 2 + 1], A1, bb + 2);
            }
            if (ni == 0) {
                unsigned b2[2];
                ldsm2(b2[0], b2[1], Vs[b] + (32 + rB2) * 272 + (kk * 16 + cB2) * 2);
                mma16816(acc[0][4], A0, b2);
                mma16816(acc[1][4], A1, b2);
            }
        }
    }
    __syncthreads();
    __half* T = (__half*)Vs[0];
#pragma unroll
    for (int mf = 0; mf < 2; mf++) {
        int r = mi * 32 + mf * 16 + (lane >> 2);
        for (int nf = 0; nf < nfr; nf++) {
            int c = noff + nf * 8 + (lane & 3) * 2;
            T[c * 72 + r]           = __float2half(acc[mf][nf][0]);
            T[(c + 1) * 72 + r]     = __float2half(acc[mf][nf][1]);
            T[c * 72 + r + 8]       = __float2half(acc[mf][nf][2]);
            T[(c + 1) * 72 + r + 8] = __float2half(acc[mf][nf][3]);
        }
    }
    __syncthreads();
    for (int idx = tid; idx < 136 * 8; idx += 256) {
        int d = idx >> 3, c8 = (idx & 7) * 8;
        *(uint4*)&g_CVt[(size_t)d * NTOK + bm + c8] = *(uint4*)&T[d * 72 + c8];
    }
}

// ---------------- fused attention: register-resident P, 128 thr, 4 warps x 16 rows ----------------
// smem: Ks[2] [64keys][272B] @0,17408 | CVs[2] [136][144B] @34816,54400. Total 73984 -> 2-3 CTAs/SM.
__global__ void __launch_bounds__(128) fa_kernel() {
    extern __shared__ char sm[];
    char* Ks[2] = {sm, sm + 17408};
    char* CVs[2] = {sm + 34816, sm + 54400};
    const int tid = threadIdx.x, lane = tid & 31, w = tid >> 5;
    const int bm = blockIdx.x * 64;
    const int jbase = blockIdx.y * (NTOK / FA_NSPLIT);
    const int NIT = (NTOK / FA_NSPLIT) / 64;   // 64 iters of 64 keys

    const int rA = ((lane >> 3) & 1) * 8 + (lane & 7);
    const int cA = ((lane >> 4) & 1) * 8;
    const int rB = ((lane >> 4) & 1) * 8 + (lane & 7);
    const int cB = ((lane >> 3) & 1) * 8;
    const int rB2 = lane & 7;
    const int cB2 = ((lane >> 3) & 1) * 8;

    // stage Q rows [bm..bm+64) into Ks[0], extract A fragments (full k=128), then free it
#pragma unroll
    for (int i = 0; i < 8; i++) {
        int idx = tid + i * 128, r = idx >> 4, c = idx & 15;
        *(uint4*)(Ks[0] + r * 272 + c * 16) = *(const uint4*)&g_Q[(size_t)(bm + r) * DIM + c * 8];
    }
    __syncthreads();
    unsigned aq[8][4];
#pragma unroll
    for (int kf = 0; kf < 8; kf++)
        ldsm4(aq[kf][0], aq[kf][1], aq[kf][2], aq[kf][3],
              Ks[0] + (w * 16 + rA) * 272 + (kf * 16 + cA) * 2);
    __syncthreads();

    // issue K(0), CV(0) into buffer 0
#pragma unroll
    for (int i = 0; i < 8; i++) {
        int idx = tid + i * 128, r = idx >> 4, c = idx & 15;
        cpa16(Ks[0] + r * 272 + c * 16, &g_K[(size_t)(jbase + r) * DIM + c * 8]);
    }
#pragma unroll
    for (int i = 0; i < 9; i++) {
        int idx = tid + i * 128;
        if (idx < 136 * 8) {
            int r = idx >> 3, c = idx & 7;
            cpa16(CVs[0] + r * 144 + c * 16, &g_CVt[(size_t)r * NTOK + jbase + c * 8]);
        }
    }
    CPCOMMIT();

    float acc[17][4];
#pragma unroll
    for (int nf = 0; nf < 17; nf++)
#pragma unroll
        for (int i = 0; i < 4; i++) acc[nf][i] = 0.f;

    for (int j = 0; j < NIT; j++) {
        int b = j & 1;
        CPWAIT0();
        __syncthreads();
        // prefetch j+1 into other buffer (all warps passed compute(j-1) on it)
        if (j + 1 < NIT) {
            int jb = jbase + (j + 1) * 64;
            char* kb = Ks[b ^ 1];
            char* cv = CVs[b ^ 1];
#pragma unroll
            for (int i = 0; i < 8; i++) {
                int idx = tid + i * 128, r = idx >> 4, c = idx & 15;
                cpa16(kb + r * 272 + c * 16, &g_K[(size_t)(jb + r) * DIM + c * 8]);
            }
#pragma unroll
            for (int i = 0; i < 9; i++) {
                int idx = tid + i * 128;
                if (idx < 136 * 8) {
                    int r = idx >> 3, c = idx & 7;
                    cpa16(cv + r * 144 + c * 16, &g_CVt[(size_t)r * NTOK + jb + c * 8]);
                }
            }
            CPCOMMIT();
        }
        // phase 1: S = Q @ K^T, this warp's 16 rows x all 64 keys
        float sacc[8][4];
#pragma unroll
        for (int g = 0; g < 8; g++)
#pragma unroll
            for (int i = 0; i < 4; i++) sacc[g][i] = 0.f;
#pragma unroll
        for (int kk = 0; kk < 8; kk++) {
#pragma unroll
            for (int g = 0; g < 4; g++) {
                unsigned bb[4];
                ldsm4(bb[0], bb[1], bb[2], bb[3],
                      Ks[b] + (g * 16 + rB) * 272 + (kk * 16 + cB) * 2);
                mma16816(sacc[2 * g], aq[kk], bb);
                mma16816(sacc[2 * g + 1], aq[kk], bb + 2);
            }
        }
        // exp in regs, pack C-frags -> A-frags (P = exp(S), 16 x 64 keys)
        unsigned P[4][4];
#pragma unroll
        for (int kf = 0; kf < 4; kf++) {
            P[kf][0] = packh2(__expf(sacc[2 * kf][0]), __expf(sacc[2 * kf][1]));
            P[kf][1] = packh2(__expf(sacc[2 * kf][2]), __expf(sacc[2 * kf][3]));
            P[kf][2] = packh2(__expf(sacc[2 * kf + 1][0]), __expf(sacc[2 * kf + 1][1]));
            P[kf][3] = packh2(__expf(sacc[2 * kf + 1][2]), __expf(sacc[2 * kf + 1][3]));
        }
        // phase 2: acc += P @ CV1 (N = 136, k = 64)
#pragma unroll
        for (int kk = 0; kk < 4; kk++) {
#pragma unroll
            for (int p = 0; p < 8; p++) {
                unsigned bb[4];
                ldsm4(bb[0], bb[1], bb[2], bb[3],
                      CVs[b] + (p * 16 + rB) * 144 + (kk * 16 + cB) * 2);
                mma16816(acc[2 * p], P[kk], bb);
                mma16816(acc[2 * p + 1], P[kk], bb + 2);
            }
            unsigned b2[2];
            ldsm2(b2[0], b2[1], CVs[b] + (128 + rB2) * 144 + (kk * 16 + cB2) * 2);
            mma16816(acc[16], P[kk], b2);
        }
    }
    // store fp32 partials [split][row][144]
    {
        int row = bm + w * 16 + (lane >> 2);
        size_t base = ((size_t)blockIdx.y * NTOK + row) * 144;
#pragma unroll
        for (int nf = 0; nf < 17; nf++) {
            int c = nf * 8 + (lane & 3) * 2;
            *(float2*)&g_scr[base + c]           = make_float2(acc[nf][0], acc[nf][1]);
            *(float2*)&g_scr[base + 8 * 144 + c] = make_float2(acc[nf][2], acc[nf][3]);
        }
    }
}

// ---------------- final reduce ----------------
__global__ void fareduce_kernel(float* __restrict__ out) {
    int m = blockIdx.x;
    int d = threadIdx.x;   // 128
    float num = 0.f, den = 0.f;
#pragma unroll
    for (int s = 0; s < FA_NSPLIT; s++) {
        size_t b = ((size_t)s * NTOK + m) * 144;
        num += g_scr[b + d];
        den += g_scr[b + 128];
    }
    out[(size_t)m * DIM + d] = elu1(num / (den + 1e-9f));
}

// ---------------- launch ----------------
extern "C" void kernel_launch(void* const* d_in, const int* in_sizes, int n_in,
                              void* d_out, int out_size) {
    const float* feat = (const float*)d_in[0];
    const float* Cg   = (const float*)d_in[2];
    const float* Wq   = (const float*)d_in[3];
    const float* Wk   = (const float*)d_in[4];
    const float* Wv   = (const float*)d_in[5];
    float* out = (float*)d_out;

    cudaFuncSetAttribute(cv_kernel, cudaFuncAttributeMaxDynamicSharedMemorySize, 91392);
    cudaFuncSetAttribute(fa_kernel, cudaFuncAttributeMaxDynamicSharedMemorySize, 73984);

    prep_feat<<<(NTOK * INDIM + 255) / 256, 256>>>(feat);
    prep_w<<<(3 * DIM * INDIM + 255) / 256, 256>>>(Wq, Wk, Wv);
    prep_vt_tail<<<(8 * NTOK + 255) / 256, 256>>>();
    qkv_kernel<<<dim3(NTOK / 128, 1, 3), 256>>>();
    cv_kernel<<<NTOK / 64, 256, 91392>>>(Cg);
    fa_kernel<<<dim3(NTOK / 64, FA_NSPLIT), 128, 73984>>>();
    fareduce_kernel<<<NTOK, DIM>>>(out);
}